// round 3
// baseline (speedup 1.0000x reference)
#include <cuda_runtime.h>

// Network24: tiny 2->2->1 synapse MLP, pointwise over B rows. 12 B/row HBM.
// R3: params gathered once into __constant__ bank (pack kernel + D2D memcpy
//     node). Main kernel: 4x LDG.128 in, 2x STG.128 out, zero param LDGs.

__constant__ float c_P[20];
__device__ float g_pack[20];

// c_P layout:
//  0..3  w00 w01 w10 w11   (fc1_tw[i][j][0])
//  4..7  p00 p01 p10 p11   (fc1_power)
//  8..9  b0 b1             (fc1_bias)
// 10..13 m0 m1 m2 m3       (m4_tw[k][0])
// 14..17 q0 q1 q2 q3       (m4_power)
// 18     bias3

__global__ void pack_params_kernel(const float* __restrict__ fc1_tw,
                                   const float* __restrict__ fc1_power,
                                   const float* __restrict__ fc1_bias,
                                   const float* __restrict__ m4_tw,
                                   const float* __restrict__ m4_power,
                                   const float* __restrict__ m4_bias3)
{
    if (threadIdx.x == 0 && blockIdx.x == 0) {
        g_pack[0]  = fc1_tw[0]; g_pack[1]  = fc1_tw[3];
        g_pack[2]  = fc1_tw[6]; g_pack[3]  = fc1_tw[9];
        g_pack[4]  = fc1_power[0]; g_pack[5]  = fc1_power[1];
        g_pack[6]  = fc1_power[2]; g_pack[7]  = fc1_power[3];
        g_pack[8]  = fc1_bias[0];  g_pack[9]  = fc1_bias[1];
        g_pack[10] = m4_tw[0]; g_pack[11] = m4_tw[3];
        g_pack[12] = m4_tw[6]; g_pack[13] = m4_tw[9];
        g_pack[14] = m4_power[0]; g_pack[15] = m4_power[1];
        g_pack[16] = m4_power[2]; g_pack[17] = m4_power[3];
        g_pack[18] = m4_bias3[0];
        g_pack[19] = 0.0f;
    }
}

__device__ __forceinline__ float fpow(float x, float p) {
    // powers are grid-uniform scalars; p==1 branch is warp-uniform
    return (p == 1.0f) ? x : __powf(x, p);
}

__device__ __forceinline__ float fsig(float z) {
    // sigmoid(z) = 0.5*tanh(z/2) + 0.5  -- single MUFU.TANH
    float t;
    asm("tanh.approx.f32 %0, %1;" : "=f"(t) : "f"(0.5f * z));
    return fmaf(0.5f, t, 0.5f);
}

__device__ __forceinline__ float net_row_c(float x0, float x1) {
    float h0 = fsig(fmaf(c_P[0], fpow(x0, c_P[4]),
                    fmaf(c_P[1], fpow(x1, c_P[5]), c_P[8])));
    float h1 = fsig(fmaf(c_P[2], fpow(x0, c_P[6]),
                    fmaf(c_P[3], fpow(x1, c_P[7]), c_P[9])));
    float s1 = c_P[10] * fpow(h0, c_P[14]);
    float s2 = c_P[11] * fpow(h1, c_P[15]);
    float p1 = c_P[12] * fpow(h0, c_P[16]);
    float p2 = c_P[13] * fpow(h1, c_P[17]);
    return fsig(fmaf(p1, p2, s1 + s2) + c_P[18]);
}

__global__ void __launch_bounds__(256)
net24_vec8_kernel(const float4* __restrict__ x4,  // 4 float4 = 8 rows
                  float4* __restrict__ out4,
                  int n8)
{
    int i = blockIdx.x * blockDim.x + threadIdx.x;
    if (i >= n8) return;

    // Rows 8i..8i+7 (x is [B,2] row-major); streaming loads (read-once)
    float4 a = __ldcs(x4 + 4 * i + 0);
    float4 b = __ldcs(x4 + 4 * i + 1);
    float4 c = __ldcs(x4 + 4 * i + 2);
    float4 d = __ldcs(x4 + 4 * i + 3);

    float4 r0, r1;
    r0.x = net_row_c(a.x, a.y);
    r0.y = net_row_c(a.z, a.w);
    r0.z = net_row_c(b.x, b.y);
    r0.w = net_row_c(b.z, b.w);
    r1.x = net_row_c(c.x, c.y);
    r1.y = net_row_c(c.z, c.w);
    r1.z = net_row_c(d.x, d.y);
    r1.w = net_row_c(d.z, d.w);

    __stcs(out4 + 2 * i + 0, r0);
    __stcs(out4 + 2 * i + 1, r1);
}

__global__ void net24_tail_kernel(const float2* __restrict__ x2,
                                  float* __restrict__ out,
                                  int start, int n)
{
    int i = start + blockIdx.x * blockDim.x + threadIdx.x;
    if (i >= n) return;
    float2 v = x2[i];
    out[i] = net_row_c(v.x, v.y);
}

extern "C" void kernel_launch(void* const* d_in, const int* in_sizes, int n_in,
                              void* d_out, int out_size)
{
    const float* x         = (const float*)d_in[0];
    const float* fc1_tw    = (const float*)d_in[1];
    const float* fc1_power = (const float*)d_in[2];
    const float* fc1_bias  = (const float*)d_in[3];
    const float* m4_tw     = (const float*)d_in[4];
    const float* m4_power  = (const float*)d_in[5];
    const float* m4_bias3  = (const float*)d_in[6];
    float* out = (float*)d_out;

    // 1) gather params into g_pack
    pack_params_kernel<<<1, 32>>>(fc1_tw, fc1_power, fc1_bias,
                                  m4_tw, m4_power, m4_bias3);

    // 2) D2D copy into constant bank (graph-capturable memcpy node)
    void* pack_addr = nullptr;
    cudaGetSymbolAddress(&pack_addr, g_pack);
    cudaMemcpyToSymbolAsync(c_P, pack_addr, 20 * sizeof(float), 0,
                            cudaMemcpyDeviceToDevice, 0);

    // 3) main kernel
    int B  = in_sizes[0] / 2;   // rows
    int n8 = B / 8;
    int rem_start = n8 * 8;

    if (n8 > 0) {
        int threads = 256;
        int blocks  = (n8 + threads - 1) / threads;
        net24_vec8_kernel<<<blocks, threads>>>(
            (const float4*)x, (float4*)out, n8);
    }
    if (rem_start < B) {
        int rem = B - rem_start;
        net24_tail_kernel<<<(rem + 127) / 128, 128>>>(
            (const float2*)x, out, rem_start, B);
    }
}